// round 13
// baseline (speedup 1.0000x reference)
#include <cuda_runtime.h>
#include <math.h>

// Problem constants
#define B_   2
#define C_   512
#define HW_  32768          // H*W = 128*256
#define K_   19
#define GC_  4              // channels per block (1 per warp)
#define NCT_ (C_/GC_)       // 128 channel tiles
#define NCHUNK_ 8
#define PXC_ (HW_/NCHUNK_)  // 4096 pixels per chunk
#define NIT_ (PXC_/128)     // 32 iterations per block
#define TOTALB_ (B_*NCT_*NCHUNK_)   // 2048 blocks
#define NTAIL_  (B_*2)              // 4 tail blocks

// Scratch (no cudaMalloc allowed).
// d_cen: channel-major [bt][k][c]; zero at load, re-zeroed by tail blocks.
__device__ float d_cen[B_*2*K_*C_];
__device__ float d_dots[B_*2*K_*K_];
__device__ unsigned int d_ctr1, d_ctr2;

// One S/T float4 pair routed into per-warp float2 bins (bank == f(lane): conflict-free)
#define RMW_(sv, tv, lv)                                                        \
    do {                                                                        \
        float2 v_;                                                              \
        v_ = bin[(lv).x*32 + lane]; v_.x += (sv).x; v_.y += (tv).x; bin[(lv).x*32 + lane] = v_; \
        v_ = bin[(lv).y*32 + lane]; v_.x += (sv).y; v_.y += (tv).y; bin[(lv).y*32 + lane] = v_; \
        v_ = bin[(lv).z*32 + lane]; v_.x += (sv).z; v_.y += (tv).z; bin[(lv).z*32 + lane] = v_; \
        v_ = bin[(lv).w*32 + lane]; v_.x += (sv).w; v_.y += (tv).w; bin[(lv).w*32 + lane] = v_; \
    } while (0)

// ---------------------------------------------------------------------------
// Single fused kernel.
// Phase 1 (all 2048 blocks): segment sums — lane = pixel, warp = channel,
//   depth-2 register pipeline over the bin-RMW chain; per-channel partials
//   accumulate into channel-major d_cen via atomicAdd.
// Phase 2 (last 4 arrivers): brief spin for full d_cen, then one (b,t) Gram
//   each — warp-per-(i,j), lanes coalesced over channels, L2-hot — then
//   (AFTER a block-wide sync: R12 bug was zeroing while peers still read)
//   zero own slab, arrive on ctr2.
// Phase 3 (4th arriver on ctr2): 722-entry loss, reset counters.
// Cosine is count-scale-invariant, so raw class sums suffice.
// ---------------------------------------------------------------------------
__global__ __launch_bounds__(128, 6) void fused_kernel(
    const float* __restrict__ S,
    const float* __restrict__ T,
    const int*   __restrict__ tgt,
    float*       __restrict__ out)
{
    __shared__ float2 bins[GC_][K_*32];   // 4 warps x 19x32 float2 = 19.5 KB
    __shared__ float  outb[GC_][2][K_];
    __shared__ int    srank;
    __shared__ int    slast;
    __shared__ float  red[GC_];

    int tid  = threadIdx.x;
    int lane = tid & 31;
    int warp = tid >> 5;

    int blk   = blockIdx.x;               // b*1024 + chunk*128 + ct
    int ct    = blk & (NCT_ - 1);
    int chunk = (blk >> 7) & (NCHUNK_ - 1);
    int b     = blk >> 10;
    int c     = ct * GC_ + warp;

    const float4* Sp = (const float4*)(S + ((size_t)(b*C_ + c))*HW_ + chunk*PXC_);
    const float4* Tp = (const float4*)(T + ((size_t)(b*C_ + c))*HW_ + chunk*PXC_);
    const int4*   Lp = (const int4*)(tgt + (size_t)b*HW_ + chunk*PXC_);

    float2* bin = bins[warp];
    for (int i = lane; i < K_*32; i += 32) bin[i] = make_float2(0.f, 0.f);
    __syncwarp();

    // Depth-2 software pipeline.
    float4 s0 = __ldcs(Sp + lane);
    float4 t0 = __ldcs(Tp + lane);
    int4   l0 = __ldg (Lp + lane);
    float4 s1 = __ldcs(Sp + 32 + lane);
    float4 t1 = __ldcs(Tp + 32 + lane);
    int4   l1 = __ldg (Lp + 32 + lane);

#pragma unroll 2
    for (int it = 2; it < NIT_; ++it) {
        int idx = it*32 + lane;
        float4 s2 = __ldcs(Sp + idx);
        float4 t2 = __ldcs(Tp + idx);
        int4   l2 = __ldg (Lp + idx);
        RMW_(s0, t0, l0);
        s0 = s1; t0 = t1; l0 = l1;
        s1 = s2; t1 = t2; l1 = l2;
    }
    RMW_(s0, t0, l0);
    RMW_(s1, t1, l1);
    __syncwarp();

    // Reduce 32 lanes per class; shuffle tree.
#pragma unroll
    for (int k = 0; k < K_; ++k) {
        float2 v = bin[k*32 + lane];
#pragma unroll
        for (int off = 16; off; off >>= 1) {
            v.x += __shfl_down_sync(0xffffffff, v.x, off);
            v.y += __shfl_down_sync(0xffffffff, v.y, off);
        }
        if (lane == 0) { outb[warp][0][k] = v.x; outb[warp][1][k] = v.y; }
    }
    __syncwarp();

    // Channel-major accumulate: d_cen[((b*2+t)*K + k)*C + c].
    for (int i = lane; i < 2*K_; i += 32) {   // 38 outputs > 32 lanes: loop
        int t = i >= K_;
        int k = i - t*K_;
        atomicAdd(&d_cen[((size_t)(b*2 + t)*K_ + k)*C_ + c], outb[warp][t][k]);
    }

    // --- Arrival: last NTAIL_ blocks become the tail ---
    __threadfence();
    __syncthreads();
    if (tid == 0) srank = (int)atomicAdd(&d_ctr1, 1u);
    __syncthreads();
    int rank = srank;
    if (rank < TOTALB_ - NTAIL_) return;

    int bt = rank - (TOTALB_ - NTAIL_);   // 0..3

    if (tid == 0) {
        while (atomicAdd(&d_ctr1, 0u) < TOTALB_) __nanosleep(32);
    }
    __syncthreads();
    __threadfence();

    // --- Phase 2: Gram for this bt. warp-per-pair, lanes over channels. ---
    const float* cen = d_cen + (size_t)bt*K_*C_;
    for (int p = warp; p < K_*K_; p += GC_) {   // ~90 pairs per warp
        int i = p / K_, j = p % K_;
        const float* ri = cen + (size_t)i*C_;
        const float* rj = cen + (size_t)j*C_;
        float acc = 0.f;
#pragma unroll
        for (int m = 0; m < C_/32; ++m)          // 16 coalesced, independent loads
            acc += __ldg(ri + m*32 + lane) * __ldg(rj + m*32 + lane);
#pragma unroll
        for (int off = 16; off; off >>= 1)
            acc += __shfl_down_sync(0xffffffff, acc, off);
        if (lane == 0) d_dots[(size_t)bt*K_*K_ + p] = acc;
    }

    // R12 BUG FIX: all warps must finish READING cen before anyone zeroes it.
    __syncthreads();

    // Zero own slab for the next graph replay (only this block reads it).
    for (int i = tid; i < K_*C_; i += 128)
        d_cen[(size_t)bt*K_*C_ + i] = 0.f;

    __threadfence();
    __syncthreads();
    if (tid == 0) slast = ((int)atomicAdd(&d_ctr2, 1u) == NTAIL_ - 1);
    __syncthreads();
    if (!slast) return;
    __threadfence();

    // --- Phase 3: loss over 722 (b,i,j) entries ---
    float v = 0.f;
    for (int p = tid; p < B_*K_*K_; p += 128) {
        int j = p % K_; int r = p / K_;
        int i = r % K_; int bb = r / K_;
        const float* dS = d_dots + (size_t)(bb*2 + 0)*K_*K_;
        const float* dT = d_dots + (size_t)(bb*2 + 1)*K_*K_;
        float nSi = fmaxf(sqrtf(dS[i*K_ + i]), 1e-8f);
        float nSj = fmaxf(sqrtf(dS[j*K_ + j]), 1e-8f);
        float pS  = dS[i*K_ + j] / (nSi * nSj);
        float nTi = fmaxf(sqrtf(dT[i*K_ + i]), 1e-8f);
        float nTj = fmaxf(sqrtf(dT[j*K_ + j]), 1e-8f);
        float pT  = dT[i*K_ + j] / (nTi * nTj);
        float df  = pS - pT;
        v += df * df;
    }
#pragma unroll
    for (int off = 16; off; off >>= 1)
        v += __shfl_down_sync(0xffffffff, v, off);
    if (lane == 0) red[warp] = v;
    __syncthreads();
    if (tid == 0) {
        float s = red[0] + red[1] + red[2] + red[3];
        out[0]  = s / (float)(B_*K_*K_);
        d_ctr1 = 0;                       // reset for next graph replay
        d_ctr2 = 0;
    }
}

// ---------------------------------------------------------------------------
extern "C" void kernel_launch(void* const* d_in, const int* in_sizes, int n_in,
                              void* d_out, int out_size)
{
    const float* S   = (const float*)d_in[0];   // preds_S [2,512,128,256] f32
    const float* T   = (const float*)d_in[1];   // preds_T [2,512,128,256] f32
    const int*   tgt = (const int*)  d_in[2];   // target  [2,1,128,256] i32
    float* out = (float*)d_out;                 // scalar f32

    fused_kernel<<<TOTALB_, 128>>>(S, T, tgt, out);   // single launch
}